// round 7
// baseline (speedup 1.0000x reference)
#include <cuda_runtime.h>
#include <math.h>

#define VV      50257
#define NT      256
#define WCAPG   2048                 // global per-row winner cap
#define FCAP    256                  // finalist buffer
#define TOPK    100
#define CS_LO   32                   // sample-count target window
#define CS_HI   128
#define SEG     4
#define SEGLEN  12565
#define MAXN    8192

__device__ float    g_a[MAXN];
__device__ float    g_b[MAXN];
__device__ float    g_part[MAXN * SEG];
__device__ float    g_thr[MAXN];
__device__ unsigned g_cnt[MAXN];
__device__ unsigned g_maxi[MAXN];
__device__ float    g_win[(size_t)MAXN * WCAPG];

// ordered-int encoding for float atomicMax
__device__ __forceinline__ unsigned fkey(float f) {
    unsigned b = __float_as_uint(f);
    return (b & 0x80000000u) ? ~b : (b | 0x80000000u);
}
__device__ __forceinline__ float funkey(unsigned k) {
    return __uint_as_float((k & 0x80000000u) ? (k & 0x7FFFFFFFu) : ~k);
}

// 2^y via round-to-int bit trick + degree-5 poly; FMA/ALU only, no MUFU.
__device__ __forceinline__ float exp2_fast(float y) {
    y = fmaxf(y, -120.0f);
    float r = y + 12582912.0f;
    int   n = __float_as_int(r) - 0x4B400000;
    float f = y - (r - 12582912.0f);
    float p = 1.3333558146428443e-3f;
    p = fmaf(p, f, 9.6181291076284772e-3f);
    p = fmaf(p, f, 5.5504108664821580e-2f);
    p = fmaf(p, f, 2.4022650695910071e-1f);
    p = fmaf(p, f, 6.9314718055994531e-1f);
    p = fmaf(p, f, 1.0f);
    return __uint_as_float(__float_as_uint(p) + ((unsigned)n << 23));
}

// ---------------- block reductions (8 warps, 256 threads) ----------------
__device__ __forceinline__ float blockMaxF(float v, float* red, int tid) {
    int lane = tid & 31, w = tid >> 5;
    #pragma unroll
    for (int k = 16; k; k >>= 1) v = fmaxf(v, __shfl_xor_sync(~0u, v, k));
    if (lane == 0) red[w] = v;
    __syncthreads();
    if (tid < 32) {
        float m = (tid < 8) ? red[tid] : -INFINITY;
        #pragma unroll
        for (int k = 4; k; k >>= 1) m = fmaxf(m, __shfl_xor_sync(~0u, m, k));
        if (tid == 0) red[0] = m;
    }
    __syncthreads();
    float r = red[0]; __syncthreads();
    return r;
}
__device__ __forceinline__ int blockSumI(int v, int* redi, int tid) {
    int lane = tid & 31, w = tid >> 5;
    #pragma unroll
    for (int k = 16; k; k >>= 1) v += __shfl_xor_sync(~0u, v, k);
    if (lane == 0) redi[w] = v;
    __syncthreads();
    if (tid < 32) {
        int s = (tid < 8) ? redi[tid] : 0;
        #pragma unroll
        for (int k = 4; k; k >>= 1) s += __shfl_xor_sync(~0u, s, k);
        if (tid == 0) redi[0] = s;
    }
    __syncthreads();
    int r = redi[0]; __syncthreads();
    return r;
}

// full-row count of (> t) from global (fallback only)
__device__ __forceinline__ int cgtGlobal(const float* __restrict__ x, float t,
                                         int tid, int* redi) {
    int c = 0;
    #pragma unroll 8
    for (int i = tid; i < VV; i += NT) c += (__ldg(x + i) > t);
    return blockSumI(c, redi, tid);
}

// =================== K0: per-row sample -> threshold; init counters ===================
extern __shared__ float smk0[];

__global__ void __launch_bounds__(NT)
k0_thresh(const float* __restrict__ inp)
{
    float* samp = smk0;                 // [4096]
    __shared__ float redf[8];
    __shared__ int   redi[8];
    const int tid = threadIdx.x;
    const int row = blockIdx.x;
    const float* x = inp + (size_t)row * VV;

    float sx = -INFINITY;
    #pragma unroll
    for (int j = 0; j < 16; j++) {
        float s = __ldg(x + j * NT + tid);
        samp[j * NT + tid] = s;
        sx = fmaxf(sx, s);
    }
    float sampmax = blockMaxF(sx, redf, tid);

    auto countSamp = [&](float v) {
        int c = 0;
        #pragma unroll
        for (int j = 0; j < 16; j++) c += (samp[j * NT + tid] > v);
        return blockSumI(c, redi, tid);
    };
    float gap = 4.0f, lo = sampmax - gap, hi = sampmax;
    int clo = countSamp(lo);
    for (int e = 0; e < 16 && clo < CS_LO; e++) {
        gap *= 4.0f; lo = sampmax - gap;
        clo = countSamp(lo);
    }
    float t = lo;
    if (clo > CS_HI) {
        int found = 0;
        for (int it = 0; it < 24 && !found; it++) {
            float mid = 0.5f * (lo + hi);
            if (mid <= lo || mid >= hi) { t = hi; break; }     // tie plateau
            int c = countSamp(mid);
            if (c >= CS_LO && c <= CS_HI) { t = mid; found = 1; }
            else if (c > CS_HI) lo = mid; else hi = mid;
        }
        if (!found && t == lo) t = hi;
    }
    if (tid == 0) {
        g_thr[row]  = t;
        g_cnt[row]  = 0u;
        g_maxi[row] = 0u;       // below fkey of any real float
    }
}

// =================== K1: pure segmented stream-gather ===================
__global__ void __launch_bounds__(NT)
k1_gather(const float* __restrict__ inp)
{
    const int row = blockIdx.x >> 2;
    const int seg = blockIdx.x & 3;
    const int tid = threadIdx.x;
    const float* x = inp + (size_t)row * VV;
    const float t = __ldg(&g_thr[row]);
    const int s0 = seg * SEGLEN;
    const int s1 = min(VV, s0 + SEGLEN);
    __shared__ float redf[8];

    #define PUSH(v) do { unsigned p = atomicAdd(&g_cnt[row], 1u); \
                         if (p < WCAPG) g_win[(size_t)row * WCAPG + p] = (v); } while (0)

    float mx = -INFINITY;
    {
        int al = (int)(((size_t)row * VV + s0) & 3);
        int head = (4 - al) & 3;
        if (head > s1 - s0) head = s1 - s0;
        if (tid < head) {
            float v = __ldg(x + s0 + tid);
            mx = fmaxf(mx, v);
            if (v > t) PUSH(v);
        }
        const float4* x4 = (const float4*)(x + s0 + head);
        const int n4 = (s1 - s0 - head) >> 2;
        const int kfull = n4 >> 10;

        #define CHECKQ(q) do { \
            if (q.x > t) PUSH(q.x); \
            if (q.y > t) PUSH(q.y); \
            if (q.z > t) PUSH(q.z); \
            if (q.w > t) PUSH(q.w); \
        } while (0)

        #pragma unroll 1
        for (int k = 0; k < kfull; k++) {
            int base = (k << 10) + tid;
            float4 q0 = __ldg(x4 + base);
            float4 q1 = __ldg(x4 + base + 256);
            float4 q2 = __ldg(x4 + base + 512);
            float4 q3 = __ldg(x4 + base + 768);
            float m0 = fmaxf(fmaxf(q0.x, q0.y), fmaxf(q0.z, q0.w));
            float m1 = fmaxf(fmaxf(q1.x, q1.y), fmaxf(q1.z, q1.w));
            float m2 = fmaxf(fmaxf(q2.x, q2.y), fmaxf(q2.z, q2.w));
            float m3 = fmaxf(fmaxf(q3.x, q3.y), fmaxf(q3.z, q3.w));
            float bmx = fmaxf(fmaxf(m0, m1), fmaxf(m2, m3));
            mx = fmaxf(mx, bmx);
            if (bmx > t) { CHECKQ(q0); CHECKQ(q1); CHECKQ(q2); CHECKQ(q3); }
        }
        #pragma unroll 1
        for (int i = (kfull << 10) + tid; i < n4; i += NT) {
            float4 q = __ldg(x4 + i);
            float m0 = fmaxf(fmaxf(q.x, q.y), fmaxf(q.z, q.w));
            mx = fmaxf(mx, m0);
            if (m0 > t) CHECKQ(q);
        }
        #undef CHECKQ
        for (int i = s0 + head + (n4 << 2) + tid; i < s1; i += NT) {
            float v = __ldg(x + i);
            mx = fmaxf(mx, v);
            if (v > t) PUSH(v);
        }
    }
    #undef PUSH
    float M = blockMaxF(mx, redf, tid);
    if (tid == 0) atomicMax(&g_maxi[row], fkey(M));
}

// =================== K1b: per-row select + sort + MLP ===================
extern __shared__ float smk1b[];

__global__ void __launch_bounds__(NT)
k1b_sortmlp(const float* __restrict__ inp,
            const float* __restrict__ W1, const float* __restrict__ b1,
            const float* __restrict__ W2, const float* __restrict__ b2,
            const float* __restrict__ W3, const float* __restrict__ b3)
{
    float* win = smk1b;               // [WCAPG]
    float* buf = smk1b + WCAPG;       // [FCAP]
    __shared__ float redf[8];
    __shared__ int   redi[8];
    __shared__ int   sCnt;
    __shared__ float sh1[5];

    const int tid  = threadIdx.x;
    const int lane = tid & 31;
    const int wid  = tid >> 5;
    const int row  = blockIdx.x;
    const float* x = inp + (size_t)row * VV;

    const unsigned cntRaw = g_cnt[row];
    const float M = funkey(g_maxi[row]);
    float tSel = g_thr[row];
    int cnt = (int)min(cntRaw, (unsigned)WCAPG);

    for (int i = tid; i < cnt; i += NT) win[i] = g_win[(size_t)row * WCAPG + i];
    if (tid == 0) sCnt = 0;
    __syncthreads();

    const int bad = (cntRaw > (unsigned)WCAPG) || (cnt < TOPK);
    if (bad) {
        // ---- rare exact fallback: global bisection, gather straight into buf ----
        float gap = 8.0f, lo = M - gap, hi = M;
        int c = cgtGlobal(x, lo, tid, redi);
        for (int e = 0; e < 12 && c < TOPK; e++) {
            gap *= 4.0f; lo = M - gap;
            c = cgtGlobal(x, lo, tid, redi);
        }
        float ts = hi; int found = 0;
        if (c >= TOPK && c <= FCAP) { ts = lo; found = 1; }
        for (int it = 0; it < 50 && !found; it++) {
            float mid = 0.5f * (lo + hi);
            if (mid <= lo || mid >= hi) break;        // tie plateau -> hi
            c = cgtGlobal(x, mid, tid, redi);
            if (c >= TOPK && c <= FCAP) { ts = mid; found = 1; }
            else if (c > FCAP) lo = mid; else hi = mid;
        }
        tSel = ts;
        #pragma unroll 4
        for (int i = tid; i < VV; i += NT) {
            float v = __ldg(x + i);
            if (v > tSel) { int p = atomicAdd(&sCnt, 1); if (p < FCAP) buf[p] = v; }
        }
        __syncthreads();
    } else {
        // ---- bisect on smem winners to land count in [TOPK, FCAP] ----
        if (cnt > FCAP) {
            float lo = tSel, hi = M;
            int found = 0;
            float ts = tSel;
            for (int it = 0; it < 40 && !found; it++) {
                float mid = 0.5f * (lo + hi);
                if (mid <= lo || mid >= hi) { ts = hi; break; }   // tie plateau
                int c = 0;
                for (int i = tid; i < cnt; i += NT) c += (win[i] > mid);
                c = blockSumI(c, redi, tid);
                if (c >= TOPK && c <= FCAP) { ts = mid; found = 1; }
                else if (c > FCAP) lo = mid; else hi = mid;
            }
            if (!found && ts == tSel) ts = hi;
            tSel = ts;
        }
        for (int i = tid; i < cnt; i += NT) {
            float v = win[i];
            if (v > tSel) { int p = atomicAdd(&sCnt, 1); if (p < FCAP) buf[p] = v; }
        }
        __syncthreads();
    }

    int bc = min(sCnt, FCAP);
    if (tid >= bc) buf[tid] = -INFINITY;          // pad (NT == FCAP)
    __syncthreads();

    // ---- bitonic sort 256 descending ----
    #pragma unroll 1
    for (int k = 2; k <= FCAP; k <<= 1) {
        #pragma unroll 1
        for (int j = k >> 1; j > 0; j >>= 1) {
            int i = tid, ixj = i ^ j;
            if (ixj > i) {
                float va = buf[i], vb = buf[ixj];
                bool desc = ((i & k) == 0);
                if (desc ? (va < vb) : (va > vb)) { buf[i] = vb; buf[ixj] = va; }
            }
            __syncthreads();
        }
    }
    // tie-plateau fill: missing top-k entries equal tSel by construction
    if (tid < TOPK && tid >= bc) buf[tid] = tSel;
    __syncthreads();

    // ---- tiny MLP -> temperature -> (a, b) ----
    if (wid < 5) {
        float acc = 0.0f;
        #pragma unroll
        for (int i = lane; i < TOPK; i += 32)
            acc = fmaf(__ldg(W1 + wid * TOPK + i), buf[i], acc);
        #pragma unroll
        for (int k = 16; k; k >>= 1) acc += __shfl_xor_sync(~0u, acc, k);
        if (lane == 0) sh1[wid] = fmaxf(acc + __ldg(b1 + wid), 0.0f);
    }
    __syncthreads();
    if (tid == 0) {
        float h2[5];
        #pragma unroll
        for (int j = 0; j < 5; ++j) {
            float a2 = __ldg(b2 + j);
            #pragma unroll
            for (int i = 0; i < 5; ++i) a2 = fmaf(__ldg(W2 + j * 5 + i), sh1[i], a2);
            h2[j] = fmaxf(a2, 0.0f);
        }
        float t0 = __ldg(b3);
        #pragma unroll
        for (int i = 0; i < 5; ++i) t0 = fmaf(__ldg(W3 + i), h2[i], t0);
        t0 = fabsf(t0);
        float sp   = (t0 > 20.0f) ? t0 : log1pf(expf(t0));
        float temp = fmaxf(sp, 1e-5f);
        float a    = 1.44269504088896340736f / temp;
        g_a[row] = a;
        g_b[row] = -M * a;
    }
}

// =================== K2: segmented sum of exp (unchanged, proven) ===================
__global__ void __launch_bounds__(NT)
k2_sumexp(const float* __restrict__ inp)
{
    const int row = blockIdx.x >> 2;
    const int seg = blockIdx.x & 3;
    const int tid = threadIdx.x;
    const float* x = inp + (size_t)row * VV;
    const float a = __ldg(&g_a[row]);
    const float b = __ldg(&g_b[row]);
    const int start = seg * SEGLEN;
    const int end   = min(VV, start + SEGLEN);

    float s = 0.0f;
    int i = start + tid;
    for (; i + 7 * NT < end; i += 8 * NT) {
        float v[8];
        #pragma unroll
        for (int j = 0; j < 8; j++) v[j] = __ldg(x + i + j * NT);
        #pragma unroll
        for (int j = 0; j < 8; j++) s += exp2_fast(fmaf(v[j], a, b));
    }
    for (; i < end; i += NT) s += exp2_fast(fmaf(__ldg(x + i), a, b));

    __shared__ float red[8];
    int lane = tid & 31, w = tid >> 5;
    #pragma unroll
    for (int k = 16; k; k >>= 1) s += __shfl_xor_sync(~0u, s, k);
    if (lane == 0) red[w] = s;
    __syncthreads();
    if (tid == 0) {
        float tot = 0.0f;
        #pragma unroll
        for (int k = 0; k < NT / 32; k++) tot += red[k];
        g_part[row * SEG + seg] = tot;
    }
}

__global__ void k3_final(const float* __restrict__ inp,
                         const int* __restrict__ tokens,
                         float* __restrict__ out, int nrows)
{
    int r = blockIdx.x * blockDim.x + threadIdx.x;
    if (r >= nrows) return;
    float s = g_part[r * SEG + 0] + g_part[r * SEG + 1]
            + g_part[r * SEG + 2] + g_part[r * SEG + 3];
    int tok = tokens[r];
    tok = (tok < 0) ? 0 : ((tok >= VV) ? VV - 1 : tok);
    float xt = __ldg(inp + (size_t)r * VV + tok);
    out[r] = exp2_fast(fmaf(xt, g_a[r], g_b[r])) / s;
}

extern "C" void kernel_launch(void* const* d_in, const int* in_sizes, int n_in,
                              void* d_out, int out_size)
{
    const float* inp    = (const float*)d_in[0];
    const int*   tokens = (const int*)d_in[1];
    const float* W1     = (const float*)d_in[2];
    const float* b1     = (const float*)d_in[3];
    const float* W2     = (const float*)d_in[4];
    const float* b2     = (const float*)d_in[5];
    const float* W3     = (const float*)d_in[6];
    const float* b3     = (const float*)d_in[7];
    float*       o      = (float*)d_out;

    int N = in_sizes[1];
    if (N > MAXN) N = MAXN;

    k0_thresh <<<N, NT, 4096 * sizeof(float)>>>(inp);
    k1_gather <<<N * SEG, NT>>>(inp);
    k1b_sortmlp<<<N, NT, (WCAPG + FCAP) * sizeof(float)>>>(inp, W1, b1, W2, b2, W3, b3);
    k2_sumexp <<<N * SEG, NT>>>(inp);
    k3_final  <<<(N + 255) / 256, 256>>>(inp, tokens, o, N);
}

// round 8
// speedup vs baseline: 2.0289x; 2.0289x over previous
#include <cuda_runtime.h>
#include <math.h>

#define VV      50257
#define NT      256
#define SCAP    512                  // per-CTA smem winner staging
#define WCAPG   2048                 // global per-row winner cap (4 CTAs x SCAP)
#define FCAP    256                  // finalist buffer
#define TOPK    100
#define CS_LO   16                   // sample-count target window
#define CS_HI   48
#define SEG     4
#define SEGLEN  12565
#define MAXN    8192

__device__ float    g_a[MAXN];
__device__ float    g_b[MAXN];
__device__ float    g_part[MAXN * SEG];
__device__ float    g_thr[MAXN];
__device__ unsigned g_cnt[MAXN];
__device__ unsigned g_maxi[MAXN];
__device__ float    g_win[(size_t)MAXN * WCAPG];

// ordered-int encoding for float atomicMax
__device__ __forceinline__ unsigned fkey(float f) {
    unsigned b = __float_as_uint(f);
    return (b & 0x80000000u) ? ~b : (b | 0x80000000u);
}
__device__ __forceinline__ float funkey(unsigned k) {
    return __uint_as_float((k & 0x80000000u) ? (k & 0x7FFFFFFFu) : ~k);
}

// 2^y via round-to-int bit trick + degree-5 poly; FMA/ALU only, no MUFU.
__device__ __forceinline__ float exp2_fast(float y) {
    y = fmaxf(y, -120.0f);
    float r = y + 12582912.0f;
    int   n = __float_as_int(r) - 0x4B400000;
    float f = y - (r - 12582912.0f);
    float p = 1.3333558146428443e-3f;
    p = fmaf(p, f, 9.6181291076284772e-3f);
    p = fmaf(p, f, 5.5504108664821580e-2f);
    p = fmaf(p, f, 2.4022650695910071e-1f);
    p = fmaf(p, f, 6.9314718055994531e-1f);
    p = fmaf(p, f, 1.0f);
    return __uint_as_float(__float_as_uint(p) + ((unsigned)n << 23));
}

// ---------------- block reductions (8 warps, 256 threads) ----------------
__device__ __forceinline__ float blockMaxF(float v, float* red, int tid) {
    int lane = tid & 31, w = tid >> 5;
    #pragma unroll
    for (int k = 16; k; k >>= 1) v = fmaxf(v, __shfl_xor_sync(~0u, v, k));
    if (lane == 0) red[w] = v;
    __syncthreads();
    if (tid < 32) {
        float m = (tid < 8) ? red[tid] : -INFINITY;
        #pragma unroll
        for (int k = 4; k; k >>= 1) m = fmaxf(m, __shfl_xor_sync(~0u, m, k));
        if (tid == 0) red[0] = m;
    }
    __syncthreads();
    float r = red[0]; __syncthreads();
    return r;
}
__device__ __forceinline__ int blockSumI(int v, int* redi, int tid) {
    int lane = tid & 31, w = tid >> 5;
    #pragma unroll
    for (int k = 16; k; k >>= 1) v += __shfl_xor_sync(~0u, v, k);
    if (lane == 0) redi[w] = v;
    __syncthreads();
    if (tid < 32) {
        int s = (tid < 8) ? redi[tid] : 0;
        #pragma unroll
        for (int k = 4; k; k >>= 1) s += __shfl_xor_sync(~0u, s, k);
        if (tid == 0) redi[0] = s;
    }
    __syncthreads();
    int r = redi[0]; __syncthreads();
    return r;
}

// full-row count of (> t) from global (fallback only)
__device__ __forceinline__ int cgtGlobal(const float* __restrict__ x, float t,
                                         int tid, int* redi) {
    int c = 0;
    #pragma unroll 8
    for (int i = tid; i < VV; i += NT) c += (__ldg(x + i) > t);
    return blockSumI(c, redi, tid);
}

// =================== K0: per-row sample -> threshold; init counters ===================
extern __shared__ float smk0[];

__global__ void __launch_bounds__(NT)
k0_thresh(const float* __restrict__ inp)
{
    float* samp = smk0;                 // [4096]
    __shared__ float redf[8];
    __shared__ int   redi[8];
    const int tid = threadIdx.x;
    const int row = blockIdx.x;
    const float* x = inp + (size_t)row * VV;

    float sx = -INFINITY;
    #pragma unroll
    for (int j = 0; j < 16; j++) {
        float s = __ldg(x + j * NT + tid);
        samp[j * NT + tid] = s;
        sx = fmaxf(sx, s);
    }
    float sampmax = blockMaxF(sx, redf, tid);

    auto countSamp = [&](float v) {
        int c = 0;
        #pragma unroll
        for (int j = 0; j < 16; j++) c += (samp[j * NT + tid] > v);
        return blockSumI(c, redi, tid);
    };
    float gap = 4.0f, lo = sampmax - gap, hi = sampmax;
    int clo = countSamp(lo);
    for (int e = 0; e < 16 && clo < CS_LO; e++) {
        gap *= 4.0f; lo = sampmax - gap;
        clo = countSamp(lo);
    }
    float t = lo;
    if (clo > CS_HI) {
        int found = 0;
        for (int it = 0; it < 24 && !found; it++) {
            float mid = 0.5f * (lo + hi);
            if (mid <= lo || mid >= hi) { t = hi; break; }     // tie plateau
            int c = countSamp(mid);
            if (c >= CS_LO && c <= CS_HI) { t = mid; found = 1; }
            else if (c > CS_HI) lo = mid; else hi = mid;
        }
        if (!found && t == lo) t = hi;
    }
    if (tid == 0) {
        g_thr[row]  = t;
        g_cnt[row]  = 0u;
        g_maxi[row] = 0u;       // below fkey of any real float
    }
}

// =================== K1: pure segmented stream-gather (smem staging) ===================
__global__ void __launch_bounds__(NT)
k1_gather(const float* __restrict__ inp)
{
    __shared__ float    swin[SCAP];
    __shared__ int      scnt;
    __shared__ unsigned sbase;
    __shared__ float    redf[8];

    const int row = blockIdx.x >> 2;
    const int seg = blockIdx.x & 3;
    const int tid = threadIdx.x;
    const float* x = inp + (size_t)row * VV;
    const float t = __ldg(&g_thr[row]);
    const int s0 = seg * SEGLEN;
    const int s1 = min(VV, s0 + SEGLEN);

    if (tid == 0) scnt = 0;
    __syncthreads();

    #define PUSH(v) do { int p = atomicAdd(&scnt, 1); \
                         if (p < SCAP) swin[p] = (v); } while (0)

    float mx = -INFINITY;
    {
        int al = (int)(((size_t)row * VV + s0) & 3);
        int head = (4 - al) & 3;
        if (head > s1 - s0) head = s1 - s0;
        if (tid < head) {
            float v = __ldg(x + s0 + tid);
            mx = fmaxf(mx, v);
            if (v > t) PUSH(v);
        }
        const float4* x4 = (const float4*)(x + s0 + head);
        const int n4 = (s1 - s0 - head) >> 2;
        const int kfull = n4 >> 10;

        #define CHECKQ(q) do { \
            if (q.x > t) PUSH(q.x); \
            if (q.y > t) PUSH(q.y); \
            if (q.z > t) PUSH(q.z); \
            if (q.w > t) PUSH(q.w); \
        } while (0)

        #pragma unroll 1
        for (int k = 0; k < kfull; k++) {
            int base = (k << 10) + tid;
            float4 q0 = __ldg(x4 + base);
            float4 q1 = __ldg(x4 + base + 256);
            float4 q2 = __ldg(x4 + base + 512);
            float4 q3 = __ldg(x4 + base + 768);
            float m0 = fmaxf(fmaxf(q0.x, q0.y), fmaxf(q0.z, q0.w));
            float m1 = fmaxf(fmaxf(q1.x, q1.y), fmaxf(q1.z, q1.w));
            float m2 = fmaxf(fmaxf(q2.x, q2.y), fmaxf(q2.z, q2.w));
            float m3 = fmaxf(fmaxf(q3.x, q3.y), fmaxf(q3.z, q3.w));
            float bmx = fmaxf(fmaxf(m0, m1), fmaxf(m2, m3));
            mx = fmaxf(mx, bmx);
            if (bmx > t) { CHECKQ(q0); CHECKQ(q1); CHECKQ(q2); CHECKQ(q3); }
        }
        #pragma unroll 1
        for (int i = (kfull << 10) + tid; i < n4; i += NT) {
            float4 q = __ldg(x4 + i);
            float m0 = fmaxf(fmaxf(q.x, q.y), fmaxf(q.z, q.w));
            mx = fmaxf(mx, m0);
            if (m0 > t) CHECKQ(q);
        }
        #undef CHECKQ
        for (int i = s0 + head + (n4 << 2) + tid; i < s1; i += NT) {
            float v = __ldg(x + i);
            mx = fmaxf(mx, v);
            if (v > t) PUSH(v);
        }
    }
    #undef PUSH

    float M = blockMaxF(mx, redf, tid);   // syncs: scnt final below
    int c = scnt;

    // one global reservation per CTA; overflow forces the bad flag
    if (tid == 0) {
        if (c > SCAP) sbase = atomicAdd(&g_cnt[row], (unsigned)(WCAPG + 1));
        else          sbase = atomicAdd(&g_cnt[row], (unsigned)c);
        atomicMax(&g_maxi[row], fkey(M));
    }
    __syncthreads();
    if (c <= SCAP) {
        unsigned base = sbase;
        for (int i = tid; i < c; i += NT) {
            unsigned p = base + (unsigned)i;
            if (p < WCAPG) g_win[(size_t)row * WCAPG + p] = swin[i];
        }
    }
}

// =================== K1b: per-row select + sort + MLP ===================
extern __shared__ float smk1b[];

__global__ void __launch_bounds__(NT)
k1b_sortmlp(const float* __restrict__ inp,
            const float* __restrict__ W1, const float* __restrict__ b1,
            const float* __restrict__ W2, const float* __restrict__ b2,
            const float* __restrict__ W3, const float* __restrict__ b3)
{
    float* win = smk1b;               // [WCAPG]
    float* buf = smk1b + WCAPG;       // [FCAP]
    __shared__ int   redi[8];
    __shared__ int   sCnt;
    __shared__ float sh1[5];

    const int tid  = threadIdx.x;
    const int lane = tid & 31;
    const int wid  = tid >> 5;
    const int row  = blockIdx.x;
    const float* x = inp + (size_t)row * VV;

    const unsigned cntRaw = g_cnt[row];
    const float M = funkey(g_maxi[row]);
    float tSel = g_thr[row];
    int cnt = (int)min(cntRaw, (unsigned)WCAPG);

    for (int i = tid; i < cnt; i += NT) win[i] = g_win[(size_t)row * WCAPG + i];
    if (tid == 0) sCnt = 0;
    __syncthreads();

    const int bad = (cntRaw > (unsigned)WCAPG) || (cnt < TOPK);
    if (bad) {
        // ---- rare exact fallback: global bisection, gather straight into buf ----
        float gap = 8.0f, lo = M - gap, hi = M;
        int c = cgtGlobal(x, lo, tid, redi);
        for (int e = 0; e < 12 && c < TOPK; e++) {
            gap *= 4.0f; lo = M - gap;
            c = cgtGlobal(x, lo, tid, redi);
        }
        float ts = hi; int found = 0;
        if (c >= TOPK && c <= FCAP) { ts = lo; found = 1; }
        for (int it = 0; it < 50 && !found; it++) {
            float mid = 0.5f * (lo + hi);
            if (mid <= lo || mid >= hi) break;        // tie plateau -> hi
            c = cgtGlobal(x, mid, tid, redi);
            if (c >= TOPK && c <= FCAP) { ts = mid; found = 1; }
            else if (c > FCAP) lo = mid; else hi = mid;
        }
        tSel = ts;
        #pragma unroll 4
        for (int i = tid; i < VV; i += NT) {
            float v = __ldg(x + i);
            if (v > tSel) { int p = atomicAdd(&sCnt, 1); if (p < FCAP) buf[p] = v; }
        }
        __syncthreads();
    } else {
        // ---- bisect on smem winners to land count in [TOPK, FCAP] ----
        if (cnt > FCAP) {
            float lo = tSel, hi = M;
            int found = 0;
            float ts = tSel;
            for (int it = 0; it < 40 && !found; it++) {
                float mid = 0.5f * (lo + hi);
                if (mid <= lo || mid >= hi) { ts = hi; break; }   // tie plateau
                int c = 0;
                for (int i = tid; i < cnt; i += NT) c += (win[i] > mid);
                c = blockSumI(c, redi, tid);
                if (c >= TOPK && c <= FCAP) { ts = mid; found = 1; }
                else if (c > FCAP) lo = mid; else hi = mid;
            }
            if (!found && ts == tSel) ts = hi;
            tSel = ts;
        }
        for (int i = tid; i < cnt; i += NT) {
            float v = win[i];
            if (v > tSel) { int p = atomicAdd(&sCnt, 1); if (p < FCAP) buf[p] = v; }
        }
        __syncthreads();
    }

    int bc = min(sCnt, FCAP);
    if (tid >= bc) buf[tid] = -INFINITY;          // pad (NT == FCAP)
    __syncthreads();

    // ---- bitonic sort 256 descending ----
    #pragma unroll 1
    for (int k = 2; k <= FCAP; k <<= 1) {
        #pragma unroll 1
        for (int j = k >> 1; j > 0; j >>= 1) {
            int i = tid, ixj = i ^ j;
            if (ixj > i) {
                float va = buf[i], vb = buf[ixj];
                bool desc = ((i & k) == 0);
                if (desc ? (va < vb) : (va > vb)) { buf[i] = vb; buf[ixj] = va; }
            }
            __syncthreads();
        }
    }
    // tie-plateau fill: missing top-k entries equal tSel by construction
    if (tid < TOPK && tid >= bc) buf[tid] = tSel;
    __syncthreads();

    // ---- tiny MLP -> temperature -> (a, b) ----
    if (wid < 5) {
        float acc = 0.0f;
        #pragma unroll
        for (int i = lane; i < TOPK; i += 32)
            acc = fmaf(__ldg(W1 + wid * TOPK + i), buf[i], acc);
        #pragma unroll
        for (int k = 16; k; k >>= 1) acc += __shfl_xor_sync(~0u, acc, k);
        if (lane == 0) sh1[wid] = fmaxf(acc + __ldg(b1 + wid), 0.0f);
    }
    __syncthreads();
    if (tid == 0) {
        float h2[5];
        #pragma unroll
        for (int j = 0; j < 5; ++j) {
            float a2 = __ldg(b2 + j);
            #pragma unroll
            for (int i = 0; i < 5; ++i) a2 = fmaf(__ldg(W2 + j * 5 + i), sh1[i], a2);
            h2[j] = fmaxf(a2, 0.0f);
        }
        float t0 = __ldg(b3);
        #pragma unroll
        for (int i = 0; i < 5; ++i) t0 = fmaf(__ldg(W3 + i), h2[i], t0);
        t0 = fabsf(t0);
        float sp   = (t0 > 20.0f) ? t0 : log1pf(expf(t0));
        float temp = fmaxf(sp, 1e-5f);
        float a    = 1.44269504088896340736f / temp;
        g_a[row] = a;
        g_b[row] = -M * a;
    }
}

// =================== K2: segmented sum of exp (unchanged, proven) ===================
__global__ void __launch_bounds__(NT)
k2_sumexp(const float* __restrict__ inp)
{
    const int row = blockIdx.x >> 2;
    const int seg = blockIdx.x & 3;
    const int tid = threadIdx.x;
    const float* x = inp + (size_t)row * VV;
    const float a = __ldg(&g_a[row]);
    const float b = __ldg(&g_b[row]);
    const int start = seg * SEGLEN;
    const int end   = min(VV, start + SEGLEN);

    float s = 0.0f;
    int i = start + tid;
    for (; i + 7 * NT < end; i += 8 * NT) {
        float v[8];
        #pragma unroll
        for (int j = 0; j < 8; j++) v[j] = __ldg(x + i + j * NT);
        #pragma unroll
        for (int j = 0; j < 8; j++) s += exp2_fast(fmaf(v[j], a, b));
    }
    for (; i < end; i += NT) s += exp2_fast(fmaf(__ldg(x + i), a, b));

    __shared__ float red[8];
    int lane = tid & 31, w = tid >> 5;
    #pragma unroll
    for (int k = 16; k; k >>= 1) s += __shfl_xor_sync(~0u, s, k);
    if (lane == 0) red[w] = s;
    __syncthreads();
    if (tid == 0) {
        float tot = 0.0f;
        #pragma unroll
        for (int k = 0; k < NT / 32; k++) tot += red[k];
        g_part[row * SEG + seg] = tot;
    }
}

__global__ void k3_final(const float* __restrict__ inp,
                         const int* __restrict__ tokens,
                         float* __restrict__ out, int nrows)
{
    int r = blockIdx.x * blockDim.x + threadIdx.x;
    if (r >= nrows) return;
    float s = g_part[r * SEG + 0] + g_part[r * SEG + 1]
            + g_part[r * SEG + 2] + g_part[r * SEG + 3];
    int tok = tokens[r];
    tok = (tok < 0) ? 0 : ((tok >= VV) ? VV - 1 : tok);
    float xt = __ldg(inp + (size_t)r * VV + tok);
    out[r] = exp2_fast(fmaf(xt, g_a[r], g_b[r])) / s;
}

extern "C" void kernel_launch(void* const* d_in, const int* in_sizes, int n_in,
                              void* d_out, int out_size)
{
    const float* inp    = (const float*)d_in[0];
    const int*   tokens = (const int*)d_in[1];
    const float* W1     = (const float*)d_in[2];
    const float* b1     = (const float*)d_in[3];
    const float* W2     = (const float*)d_in[4];
    const float* b2     = (const float*)d_in[5];
    const float* W3     = (const float*)d_in[6];
    const float* b3     = (const float*)d_in[7];
    float*       o      = (float*)d_out;

    int N = in_sizes[1];
    if (N > MAXN) N = MAXN;

    k0_thresh <<<N, NT, 4096 * sizeof(float)>>>(inp);
    k1_gather <<<N * SEG, NT>>>(inp);
    k1b_sortmlp<<<N, NT, (WCAPG + FCAP) * sizeof(float)>>>(inp, W1, b1, W2, b2, W3, b3);
    k2_sumexp <<<N * SEG, NT>>>(inp);
    k3_final  <<<(N + 255) / 256, 256>>>(inp, tokens, o, N);
}

// round 9
// speedup vs baseline: 2.0390x; 1.0050x over previous
#include <cuda_runtime.h>
#include <math.h>

#define VV      50257
#define NT      256
#define SCAP    512                  // per-CTA smem winner staging
#define WCAPG   2048                 // global per-row winner cap (4 CTAs x SCAP)
#define FCAP    512                  // finalist buffer
#define TOPK    100
#define CS_LO   24                   // sample-count target window
#define CS_HI   64
#define SEG     4
#define SEGLEN  12565
#define MAXN    8192

__device__ float    g_a[MAXN];
__device__ float    g_b[MAXN];
__device__ float    g_part[MAXN * SEG];
__device__ float    g_thr[MAXN];
__device__ unsigned g_cnt[MAXN];
__device__ unsigned g_done1[MAXN];   // zero-init; self-resetting each replay
__device__ unsigned g_done2[MAXN];   // zero-init; self-resetting each replay
__device__ float    g_win[(size_t)MAXN * WCAPG];

// 2^y via round-to-int bit trick + degree-5 poly; FMA/ALU only, no MUFU.
__device__ __forceinline__ float exp2_fast(float y) {
    y = fmaxf(y, -120.0f);
    float r = y + 12582912.0f;
    int   n = __float_as_int(r) - 0x4B400000;
    float f = y - (r - 12582912.0f);
    float p = 1.3333558146428443e-3f;
    p = fmaf(p, f, 9.6181291076284772e-3f);
    p = fmaf(p, f, 5.5504108664821580e-2f);
    p = fmaf(p, f, 2.4022650695910071e-1f);
    p = fmaf(p, f, 6.9314718055994531e-1f);
    p = fmaf(p, f, 1.0f);
    return __uint_as_float(__float_as_uint(p) + ((unsigned)n << 23));
}

// ---------------- block reductions (8 warps, 256 threads) ----------------
__device__ __forceinline__ float blockMaxF(float v, float* red, int tid) {
    int lane = tid & 31, w = tid >> 5;
    #pragma unroll
    for (int k = 16; k; k >>= 1) v = fmaxf(v, __shfl_xor_sync(~0u, v, k));
    if (lane == 0) red[w] = v;
    __syncthreads();
    if (tid < 32) {
        float m = (tid < 8) ? red[tid] : -INFINITY;
        #pragma unroll
        for (int k = 4; k; k >>= 1) m = fmaxf(m, __shfl_xor_sync(~0u, m, k));
        if (tid == 0) red[0] = m;
    }
    __syncthreads();
    float r = red[0]; __syncthreads();
    return r;
}
__device__ __forceinline__ int blockSumI(int v, int* redi, int tid) {
    int lane = tid & 31, w = tid >> 5;
    #pragma unroll
    for (int k = 16; k; k >>= 1) v += __shfl_xor_sync(~0u, v, k);
    if (lane == 0) redi[w] = v;
    __syncthreads();
    if (tid < 32) {
        int s = (tid < 8) ? redi[tid] : 0;
        #pragma unroll
        for (int k = 4; k; k >>= 1) s += __shfl_xor_sync(~0u, s, k);
        if (tid == 0) redi[0] = s;
    }
    __syncthreads();
    int r = redi[0]; __syncthreads();
    return r;
}

// full-row count of (> t) from global (fallback only)
__device__ __forceinline__ int cgtGlobal(const float* __restrict__ x, float t,
                                         int tid, int* redi) {
    int c = 0;
    #pragma unroll 8
    for (int i = tid; i < VV; i += NT) c += (__ldg(x + i) > t);
    return blockSumI(c, redi, tid);
}

// =================== K0: per-row sample -> threshold; init counters ===================
extern __shared__ float smk0[];

__global__ void __launch_bounds__(NT)
k0_thresh(const float* __restrict__ inp)
{
    float* samp = smk0;                 // [4096]
    __shared__ float redf[8];
    __shared__ int   redi[8];
    const int tid = threadIdx.x;
    const int row = blockIdx.x;
    const float* x = inp + (size_t)row * VV;

    float sx = -INFINITY;
    #pragma unroll
    for (int j = 0; j < 16; j++) {
        float s = __ldg(x + j * NT + tid);
        samp[j * NT + tid] = s;
        sx = fmaxf(sx, s);
    }
    float sampmax = blockMaxF(sx, redf, tid);

    auto countSamp = [&](float v) {
        int c = 0;
        #pragma unroll
        for (int j = 0; j < 16; j++) c += (samp[j * NT + tid] > v);
        return blockSumI(c, redi, tid);
    };
    float gap = 4.0f, lo = sampmax - gap, hi = sampmax;
    int clo = countSamp(lo);
    for (int e = 0; e < 16 && clo < CS_LO; e++) {
        gap *= 4.0f; lo = sampmax - gap;
        clo = countSamp(lo);
    }
    float t = lo;
    if (clo > CS_HI) {
        int found = 0;
        for (int it = 0; it < 24 && !found; it++) {
            float mid = 0.5f * (lo + hi);
            if (mid <= lo || mid >= hi) { t = hi; break; }     // tie plateau
            int c = countSamp(mid);
            if (c >= CS_LO && c <= CS_HI) { t = mid; found = 1; }
            else if (c > CS_HI) lo = mid; else hi = mid;
        }
        if (!found && t == lo) t = hi;
    }
    if (tid == 0) {
        g_thr[row] = t;
        g_cnt[row] = 0u;
    }
}

// =================== K1: stream-gather + last-CTA epilogue (select/sort/MLP) ===================
__global__ void __launch_bounds__(NT)
k1_gather(const float* __restrict__ inp,
          const float* __restrict__ W1, const float* __restrict__ b1,
          const float* __restrict__ W2, const float* __restrict__ b2,
          const float* __restrict__ W3, const float* __restrict__ b3)
{
    __shared__ float    pool[WCAPG + FCAP];   // staging [0,SCAP); epilogue win[0,WCAPG)+buf
    __shared__ int      scnt;
    __shared__ unsigned sbase;
    __shared__ int      sdone;
    __shared__ float    redf[8];
    __shared__ int      redi[8];
    __shared__ int      sCnt2;
    __shared__ float    sh1[5];

    const int row = blockIdx.x >> 2;
    const int seg = blockIdx.x & 3;
    const int tid = threadIdx.x;
    const int lane = tid & 31;
    const int wid  = tid >> 5;
    const float* x = inp + (size_t)row * VV;
    const float t = __ldg(&g_thr[row]);
    const int s0 = seg * SEGLEN;
    const int s1 = min(VV, s0 + SEGLEN);

    if (tid == 0) scnt = 0;
    __syncthreads();

    #define PUSH(v) do { int p = atomicAdd(&scnt, 1); \
                         if (p < SCAP) pool[p] = (v); } while (0)

    // ---- pure stream over this segment ----
    {
        int al = (int)(((size_t)row * VV + s0) & 3);
        int head = (4 - al) & 3;
        if (head > s1 - s0) head = s1 - s0;
        if (tid < head) {
            float v = __ldg(x + s0 + tid);
            if (v > t) PUSH(v);
        }
        const float4* x4 = (const float4*)(x + s0 + head);
        const int n4 = (s1 - s0 - head) >> 2;
        const int kfull = n4 >> 10;

        #define CHECKQ(q) do { \
            if (q.x > t) PUSH(q.x); \
            if (q.y > t) PUSH(q.y); \
            if (q.z > t) PUSH(q.z); \
            if (q.w > t) PUSH(q.w); \
        } while (0)

        #pragma unroll 1
        for (int k = 0; k < kfull; k++) {
            int base = (k << 10) + tid;
            float4 q0 = __ldg(x4 + base);
            float4 q1 = __ldg(x4 + base + 256);
            float4 q2 = __ldg(x4 + base + 512);
            float4 q3 = __ldg(x4 + base + 768);
            float m0 = fmaxf(fmaxf(q0.x, q0.y), fmaxf(q0.z, q0.w));
            float m1 = fmaxf(fmaxf(q1.x, q1.y), fmaxf(q1.z, q1.w));
            float m2 = fmaxf(fmaxf(q2.x, q2.y), fmaxf(q2.z, q2.w));
            float m3 = fmaxf(fmaxf(q3.x, q3.y), fmaxf(q3.z, q3.w));
            float bmx = fmaxf(fmaxf(m0, m1), fmaxf(m2, m3));
            if (bmx > t) { CHECKQ(q0); CHECKQ(q1); CHECKQ(q2); CHECKQ(q3); }
        }
        #pragma unroll 1
        for (int i = (kfull << 10) + tid; i < n4; i += NT) {
            float4 q = __ldg(x4 + i);
            float m0 = fmaxf(fmaxf(q.x, q.y), fmaxf(q.z, q.w));
            if (m0 > t) CHECKQ(q);
        }
        #undef CHECKQ
        for (int i = s0 + head + (n4 << 2) + tid; i < s1; i += NT) {
            float v = __ldg(x + i);
            if (v > t) PUSH(v);
        }
    }
    #undef PUSH

    __syncthreads();
    int c = scnt;
    if (tid == 0)
        sbase = atomicAdd(&g_cnt[row], (c > SCAP) ? (unsigned)(WCAPG + 1) : (unsigned)c);
    __syncthreads();
    if (c <= SCAP) {
        unsigned base = sbase;
        for (int i = tid; i < c; i += NT) {
            unsigned p = base + (unsigned)i;
            if (p < WCAPG) g_win[(size_t)row * WCAPG + p] = pool[i];
        }
    }
    __threadfence();
    __syncthreads();
    if (tid == 0) sdone = (int)atomicAdd(&g_done1[row], 1u);
    __syncthreads();
    if (sdone != SEG - 1) return;

    // =========== last CTA of the row: select + sort + MLP ===========
    __threadfence();
    const unsigned cntRaw = g_cnt[row];
    int cnt = (int)min(cntRaw, (unsigned)WCAPG);
    float* win = pool;
    float* buf = pool + WCAPG;

    if (tid == 0) { sCnt2 = 0; g_done1[row] = 0u; }   // reset for next replay
    const int bad = (cntRaw > (unsigned)WCAPG) || (cnt < TOPK);
    float M, tSel;

    if (bad) {
        // ---- rare exact fallback: exact max + global bisection + gather ----
        float mx = -INFINITY;
        #pragma unroll 8
        for (int i = tid; i < VV; i += NT) mx = fmaxf(mx, __ldg(x + i));
        M = blockMaxF(mx, redf, tid);                 // also syncs sCnt2
        float gap = 8.0f, lo = M - gap, hi = M;
        int cc = cgtGlobal(x, lo, tid, redi);
        for (int e = 0; e < 12 && cc < TOPK; e++) {
            gap *= 4.0f; lo = M - gap;
            cc = cgtGlobal(x, lo, tid, redi);
        }
        float ts = hi; int found = 0;
        if (cc >= TOPK && cc <= FCAP) { ts = lo; found = 1; }
        for (int it = 0; it < 50 && !found; it++) {
            float mid = 0.5f * (lo + hi);
            if (mid <= lo || mid >= hi) break;        // tie plateau -> hi
            cc = cgtGlobal(x, mid, tid, redi);
            if (cc >= TOPK && cc <= FCAP) { ts = mid; found = 1; }
            else if (cc > FCAP) lo = mid; else hi = mid;
        }
        tSel = ts;
        #pragma unroll 4
        for (int i = tid; i < VV; i += NT) {
            float v = __ldg(x + i);
            if (v > tSel) { int p = atomicAdd(&sCnt2, 1); if (p < FCAP) buf[p] = v; }
        }
        __syncthreads();
    } else {
        for (int i = tid; i < cnt; i += NT) win[i] = g_win[(size_t)row * WCAPG + i];
        __syncthreads();
        float mx = -INFINITY;
        for (int i = tid; i < cnt; i += NT) mx = fmaxf(mx, win[i]);
        M = blockMaxF(mx, redf, tid);                 // exact row max: M > t guaranteed
        tSel = t;
        if (cnt > FCAP) {
            float lo = t, hi = M;
            int found = 0;
            float ts = t;
            for (int it = 0; it < 40 && !found; it++) {
                float mid = 0.5f * (lo + hi);
                if (mid <= lo || mid >= hi) { ts = hi; break; }   // tie plateau
                int cc = 0;
                for (int i = tid; i < cnt; i += NT) cc += (win[i] > mid);
                cc = blockSumI(cc, redi, tid);
                if (cc >= TOPK && cc <= FCAP) { ts = mid; found = 1; }
                else if (cc > FCAP) lo = mid; else hi = mid;
            }
            if (!found && ts == t) ts = hi;
            tSel = ts;
        }
        for (int i = tid; i < cnt; i += NT) {
            float v = win[i];
            if (v > tSel) { int p = atomicAdd(&sCnt2, 1); if (p < FCAP) buf[p] = v; }
        }
        __syncthreads();
    }

    int bc = min(sCnt2, FCAP);
    if (tid       >= bc) buf[tid]       = -INFINITY;   // pad (FCAP == 2*NT)
    if (tid + 256 >= bc) buf[tid + 256] = -INFINITY;
    __syncthreads();

    // ---- bitonic sort 512 descending (2 elems/thread) ----
    #pragma unroll 1
    for (int k = 2; k <= FCAP; k <<= 1) {
        #pragma unroll 1
        for (int j = k >> 1; j > 0; j >>= 1) {
            #pragma unroll
            for (int mb = 0; mb < FCAP; mb += NT) {
                int i = mb + tid, ixj = i ^ j;
                if (ixj > i) {
                    float va = buf[i], vb = buf[ixj];
                    bool desc = ((i & k) == 0);
                    if (desc ? (va < vb) : (va > vb)) { buf[i] = vb; buf[ixj] = va; }
                }
            }
            __syncthreads();
        }
    }
    // tie-plateau fill: missing top-k entries equal tSel by construction
    if (tid < TOPK && tid >= bc) buf[tid] = tSel;
    __syncthreads();

    // ---- tiny MLP -> temperature -> (a, b) ----
    if (wid < 5) {
        float acc = 0.0f;
        #pragma unroll
        for (int i = lane; i < TOPK; i += 32)
            acc = fmaf(__ldg(W1 + wid * TOPK + i), buf[i], acc);
        #pragma unroll
        for (int k = 16; k; k >>= 1) acc += __shfl_xor_sync(~0u, acc, k);
        if (lane == 0) sh1[wid] = fmaxf(acc + __ldg(b1 + wid), 0.0f);
    }
    __syncthreads();
    if (tid == 0) {
        float h2[5];
        #pragma unroll
        for (int j = 0; j < 5; ++j) {
            float a2 = __ldg(b2 + j);
            #pragma unroll
            for (int i = 0; i < 5; ++i) a2 = fmaf(__ldg(W2 + j * 5 + i), sh1[i], a2);
            h2[j] = fmaxf(a2, 0.0f);
        }
        float t0 = __ldg(b3);
        #pragma unroll
        for (int i = 0; i < 5; ++i) t0 = fmaf(__ldg(W3 + i), h2[i], t0);
        t0 = fabsf(t0);
        float sp   = (t0 > 20.0f) ? t0 : log1pf(expf(t0));
        float temp = fmaxf(sp, 1e-5f);
        float a    = 1.44269504088896340736f / temp;
        g_a[row] = a;
        g_b[row] = -M * a;
    }
}

// =================== K2: sum of exp + last-CTA finalize ===================
__global__ void __launch_bounds__(NT)
k2_sumexp(const float* __restrict__ inp,
          const int* __restrict__ tokens,
          float* __restrict__ out)
{
    const int row = blockIdx.x >> 2;
    const int seg = blockIdx.x & 3;
    const int tid = threadIdx.x;
    const float* x = inp + (size_t)row * VV;
    const float a = __ldg(&g_a[row]);
    const float b = __ldg(&g_b[row]);
    const int start = seg * SEGLEN;
    const int end   = min(VV, start + SEGLEN);

    float s = 0.0f;
    int i = start + tid;
    for (; i + 7 * NT < end; i += 8 * NT) {
        float v[8];
        #pragma unroll
        for (int j = 0; j < 8; j++) v[j] = __ldg(x + i + j * NT);
        #pragma unroll
        for (int j = 0; j < 8; j++) s += exp2_fast(fmaf(v[j], a, b));
    }
    for (; i < end; i += NT) s += exp2_fast(fmaf(__ldg(x + i), a, b));

    __shared__ float red[8];
    __shared__ int   sdone;
    int lane = tid & 31, w = tid >> 5;
    #pragma unroll
    for (int k = 16; k; k >>= 1) s += __shfl_xor_sync(~0u, s, k);
    if (lane == 0) red[w] = s;
    __syncthreads();
    if (tid == 0) {
        float tot = 0.0f;
        #pragma unroll
        for (int k = 0; k < NT / 32; k++) tot += red[k];
        g_part[row * SEG + seg] = tot;
        __threadfence();
        sdone = (int)atomicAdd(&g_done2[row], 1u);
    }
    __syncthreads();
    if (sdone == SEG - 1 && tid == 0) {
        __threadfence();
        float tot = g_part[row * SEG + 0] + g_part[row * SEG + 1]
                  + g_part[row * SEG + 2] + g_part[row * SEG + 3];
        int tok = tokens[row];
        tok = (tok < 0) ? 0 : ((tok >= VV) ? VV - 1 : tok);
        float xt = __ldg(x + tok);
        out[row] = exp2_fast(fmaf(xt, a, b)) / tot;
        g_done2[row] = 0u;                          // reset for next replay
    }
}

extern "C" void kernel_launch(void* const* d_in, const int* in_sizes, int n_in,
                              void* d_out, int out_size)
{
    const float* inp    = (const float*)d_in[0];
    const int*   tokens = (const int*)d_in[1];
    const float* W1     = (const float*)d_in[2];
    const float* b1     = (const float*)d_in[3];
    const float* W2     = (const float*)d_in[4];
    const float* b2     = (const float*)d_in[5];
    const float* W3     = (const float*)d_in[6];
    const float* b3     = (const float*)d_in[7];
    float*       o      = (float*)d_out;

    int N = in_sizes[1];
    if (N > MAXN) N = MAXN;

    k0_thresh<<<N, NT, 4096 * sizeof(float)>>>(inp);
    k1_gather<<<N * SEG, NT>>>(inp, W1, b1, W2, b2, W3, b3);
    k2_sumexp<<<N * SEG, NT>>>(inp, tokens, o);
}

// round 10
// speedup vs baseline: 2.1271x; 1.0432x over previous
#include <cuda_runtime.h>
#include <math.h>

#define VV      50257
#define NT      256
#define SCAP    512                  // per-CTA smem winner staging
#define WCAPG   2048                 // global per-row winner cap (4 CTAs x SCAP)
#define FCAP    256                  // finalist buffer
#define TOPK    100
#define NSAMP   2048                 // K0 sample size (8 per thread)
#define CS_LO   12                   // sample-count target window
#define CS_HI   32
#define SEG     4
#define SEGLEN  12565
#define MAXN    8192

__device__ float    g_a[MAXN];
__device__ float    g_b[MAXN];
__device__ float    g_part[MAXN * SEG];
__device__ float    g_thr[MAXN];
__device__ unsigned g_cnt[MAXN];
__device__ unsigned g_done2[MAXN];   // zero-init; self-resetting each replay
__device__ float    g_win[(size_t)MAXN * WCAPG];

// 2^y via round-to-int bit trick + degree-5 poly; FMA/ALU only, no MUFU.
__device__ __forceinline__ float exp2_fast(float y) {
    y = fmaxf(y, -120.0f);
    float r = y + 12582912.0f;
    int   n = __float_as_int(r) - 0x4B400000;
    float f = y - (r - 12582912.0f);
    float p = 1.3333558146428443e-3f;
    p = fmaf(p, f, 9.6181291076284772e-3f);
    p = fmaf(p, f, 5.5504108664821580e-2f);
    p = fmaf(p, f, 2.4022650695910071e-1f);
    p = fmaf(p, f, 6.9314718055994531e-1f);
    p = fmaf(p, f, 1.0f);
    return __uint_as_float(__float_as_uint(p) + ((unsigned)n << 23));
}

// ---------------- block reductions (8 warps, 256 threads) ----------------
__device__ __forceinline__ float blockMaxF(float v, float* red, int tid) {
    int lane = tid & 31, w = tid >> 5;
    #pragma unroll
    for (int k = 16; k; k >>= 1) v = fmaxf(v, __shfl_xor_sync(~0u, v, k));
    if (lane == 0) red[w] = v;
    __syncthreads();
    if (tid < 32) {
        float m = (tid < 8) ? red[tid] : -INFINITY;
        #pragma unroll
        for (int k = 4; k; k >>= 1) m = fmaxf(m, __shfl_xor_sync(~0u, m, k));
        if (tid == 0) red[0] = m;
    }
    __syncthreads();
    float r = red[0]; __syncthreads();
    return r;
}
__device__ __forceinline__ int blockSumI(int v, int* redi, int tid) {
    int lane = tid & 31, w = tid >> 5;
    #pragma unroll
    for (int k = 16; k; k >>= 1) v += __shfl_xor_sync(~0u, v, k);
    if (lane == 0) redi[w] = v;
    __syncthreads();
    if (tid < 32) {
        int s = (tid < 8) ? redi[tid] : 0;
        #pragma unroll
        for (int k = 4; k; k >>= 1) s += __shfl_xor_sync(~0u, s, k);
        if (tid == 0) redi[0] = s;
    }
    __syncthreads();
    int r = redi[0]; __syncthreads();
    return r;
}

// full-row count of (> t) from global (fallback only)
__device__ __forceinline__ int cgtGlobal(const float* __restrict__ x, float t,
                                         int tid, int* redi) {
    int c = 0;
    #pragma unroll 8
    for (int i = tid; i < VV; i += NT) c += (__ldg(x + i) > t);
    return blockSumI(c, redi, tid);
}

// =================== K0: per-row 2048-sample -> threshold; init counters ===================
__global__ void __launch_bounds__(NT)
k0_thresh(const float* __restrict__ inp)
{
    __shared__ float samp[NSAMP];
    __shared__ float redf[8];
    __shared__ int   redi[8];
    const int tid = threadIdx.x;
    const int row = blockIdx.x;
    const float* x = inp + (size_t)row * VV;

    float sx = -INFINITY;
    #pragma unroll
    for (int j = 0; j < 8; j++) {
        float s = __ldg(x + j * NT + tid);
        samp[j * NT + tid] = s;
        sx = fmaxf(sx, s);
    }
    float sampmax = blockMaxF(sx, redf, tid);

    auto countSamp = [&](float v) {
        int c = 0;
        #pragma unroll
        for (int j = 0; j < 8; j++) c += (samp[j * NT + tid] > v);
        return blockSumI(c, redi, tid);
    };
    float gap = 4.0f, lo = sampmax - gap, hi = sampmax;
    int clo = countSamp(lo);
    for (int e = 0; e < 16 && clo < CS_LO; e++) {
        gap *= 4.0f; lo = sampmax - gap;
        clo = countSamp(lo);
    }
    float t = lo;
    if (clo > CS_HI) {
        int found = 0;
        for (int it = 0; it < 24 && !found; it++) {
            float mid = 0.5f * (lo + hi);
            if (mid <= lo || mid >= hi) { t = hi; break; }     // tie plateau
            int c = countSamp(mid);
            if (c >= CS_LO && c <= CS_HI) { t = mid; found = 1; }
            else if (c > CS_HI) lo = mid; else hi = mid;
        }
        if (!found && t == lo) t = hi;
    }
    if (tid == 0) {
        g_thr[row] = t;
        g_cnt[row] = 0u;
    }
}

// =================== K1: pure stream-gather, K2-shaped, pipelined loads ===================
__global__ void __launch_bounds__(NT)
k1_gather(const float* __restrict__ inp)
{
    __shared__ float    swin[SCAP];
    __shared__ int      scnt;
    __shared__ unsigned sbase;

    const int row = blockIdx.x >> 2;
    const int seg = blockIdx.x & 3;
    const int tid = threadIdx.x;
    const float* x = inp + (size_t)row * VV;
    const float t = __ldg(&g_thr[row]);
    const int s0 = seg * SEGLEN;
    const int s1 = min(VV, s0 + SEGLEN);

    if (tid == 0) scnt = 0;
    __syncthreads();

    #define PUSH(v) do { int p = atomicAdd(&scnt, 1); \
                         if (p < SCAP) swin[p] = (v); } while (0)

    const int nb = (s1 - s0) / (8 * NT);          // full 8-deep batches
    if (nb > 0) {
        float v[8];
        #pragma unroll
        for (int j = 0; j < 8; j++) v[j] = __ldg(x + s0 + tid + j * NT);
        #pragma unroll 1
        for (int k = 1; k < nb; k++) {
            float w[8];
            const int ib = s0 + k * (8 * NT) + tid;
            #pragma unroll
            for (int j = 0; j < 8; j++) w[j] = __ldg(x + ib + j * NT);  // next batch in flight
            float m8 = fmaxf(fmaxf(fmaxf(v[0], v[1]), fmaxf(v[2], v[3])),
                             fmaxf(fmaxf(v[4], v[5]), fmaxf(v[6], v[7])));
            if (m8 > t) {                          // rare (~5-12% of thread-batches)
                #pragma unroll
                for (int j = 0; j < 8; j++) if (v[j] > t) PUSH(v[j]);
            }
            #pragma unroll
            for (int j = 0; j < 8; j++) v[j] = w[j];
        }
        float m8 = fmaxf(fmaxf(fmaxf(v[0], v[1]), fmaxf(v[2], v[3])),
                         fmaxf(fmaxf(v[4], v[5]), fmaxf(v[6], v[7])));
        if (m8 > t) {
            #pragma unroll
            for (int j = 0; j < 8; j++) if (v[j] > t) PUSH(v[j]);
        }
    }
    for (int i = s0 + nb * (8 * NT) + tid; i < s1; i += NT) {   // tail
        float v = __ldg(x + i);
        if (v > t) PUSH(v);
    }
    #undef PUSH

    __syncthreads();
    int c = scnt;
    if (tid == 0)
        sbase = atomicAdd(&g_cnt[row], (c > SCAP) ? (unsigned)(WCAPG + 1) : (unsigned)c);
    __syncthreads();
    if (c <= SCAP) {
        unsigned base = sbase;
        for (int i = tid; i < c; i += NT) {
            unsigned p = base + (unsigned)i;
            if (p < WCAPG) g_win[(size_t)row * WCAPG + p] = swin[i];
        }
    }
}

// =================== K1b: per-row select + sort + MLP ===================
extern __shared__ float smk1b[];

__global__ void __launch_bounds__(NT)
k1b_sortmlp(const float* __restrict__ inp,
            const float* __restrict__ W1, const float* __restrict__ b1,
            const float* __restrict__ W2, const float* __restrict__ b2,
            const float* __restrict__ W3, const float* __restrict__ b3)
{
    float* win = smk1b;               // [WCAPG]
    float* buf = smk1b + WCAPG;       // [FCAP]
    __shared__ float redf[8];
    __shared__ int   redi[8];
    __shared__ int   sCnt;
    __shared__ float sh1[5];

    const int tid  = threadIdx.x;
    const int lane = tid & 31;
    const int wid  = tid >> 5;
    const int row  = blockIdx.x;
    const float* x = inp + (size_t)row * VV;

    const unsigned cntRaw = g_cnt[row];
    float tSel = g_thr[row];
    int cnt = (int)min(cntRaw, (unsigned)WCAPG);

    for (int i = tid; i < cnt; i += NT) win[i] = g_win[(size_t)row * WCAPG + i];
    if (tid == 0) sCnt = 0;
    __syncthreads();

    const int bad = (cntRaw > (unsigned)WCAPG) || (cnt < TOPK);
    float M;

    if (bad) {
        // ---- rare exact fallback: exact max + global bisection + gather ----
        float mx = -INFINITY;
        #pragma unroll 8
        for (int i = tid; i < VV; i += NT) mx = fmaxf(mx, __ldg(x + i));
        M = blockMaxF(mx, redf, tid);
        float gap = 8.0f, lo = M - gap, hi = M;
        int c = cgtGlobal(x, lo, tid, redi);
        for (int e = 0; e < 12 && c < TOPK; e++) {
            gap *= 4.0f; lo = M - gap;
            c = cgtGlobal(x, lo, tid, redi);
        }
        float ts = hi; int found = 0;
        if (c >= TOPK && c <= FCAP) { ts = lo; found = 1; }
        for (int it = 0; it < 50 && !found; it++) {
            float mid = 0.5f * (lo + hi);
            if (mid <= lo || mid >= hi) break;        // tie plateau -> hi
            c = cgtGlobal(x, mid, tid, redi);
            if (c >= TOPK && c <= FCAP) { ts = mid; found = 1; }
            else if (c > FCAP) lo = mid; else hi = mid;
        }
        tSel = ts;
        #pragma unroll 4
        for (int i = tid; i < VV; i += NT) {
            float v = __ldg(x + i);
            if (v > tSel) { int p = atomicAdd(&sCnt, 1); if (p < FCAP) buf[p] = v; }
        }
        __syncthreads();
    } else {
        // exact row max = max of winners (t < sampmax <= M guarantees M gathered)
        float mx = -INFINITY;
        for (int i = tid; i < cnt; i += NT) mx = fmaxf(mx, win[i]);
        M = blockMaxF(mx, redf, tid);
        if (cnt > FCAP) {
            float lo = tSel, hi = M;
            int found = 0;
            float ts = tSel;
            for (int it = 0; it < 40 && !found; it++) {
                float mid = 0.5f * (lo + hi);
                if (mid <= lo || mid >= hi) { ts = hi; break; }   // tie plateau
                int c = 0;
                for (int i = tid; i < cnt; i += NT) c += (win[i] > mid);
                c = blockSumI(c, redi, tid);
                if (c >= TOPK && c <= FCAP) { ts = mid; found = 1; }
                else if (c > FCAP) lo = mid; else hi = mid;
            }
            if (!found && ts == tSel) ts = hi;
            tSel = ts;
        }
        for (int i = tid; i < cnt; i += NT) {
            float v = win[i];
            if (v > tSel) { int p = atomicAdd(&sCnt, 1); if (p < FCAP) buf[p] = v; }
        }
        __syncthreads();
    }

    int bc = min(sCnt, FCAP);
    if (tid >= bc) buf[tid] = -INFINITY;          // pad (NT == FCAP)
    __syncthreads();

    // ---- bitonic sort 256 descending ----
    #pragma unroll 1
    for (int k = 2; k <= FCAP; k <<= 1) {
        #pragma unroll 1
        for (int j = k >> 1; j > 0; j >>= 1) {
            int i = tid, ixj = i ^ j;
            if (ixj > i) {
                float va = buf[i], vb = buf[ixj];
                bool desc = ((i & k) == 0);
                if (desc ? (va < vb) : (va > vb)) { buf[i] = vb; buf[ixj] = va; }
            }
            __syncthreads();
        }
    }
    // tie-plateau fill: missing top-k entries equal tSel by construction
    if (tid < TOPK && tid >= bc) buf[tid] = tSel;
    __syncthreads();

    // ---- tiny MLP -> temperature -> (a, b) ----
    if (wid < 5) {
        float acc = 0.0f;
        #pragma unroll
        for (int i = lane; i < TOPK; i += 32)
            acc = fmaf(__ldg(W1 + wid * TOPK + i), buf[i], acc);
        #pragma unroll
        for (int k = 16; k; k >>= 1) acc += __shfl_xor_sync(~0u, acc, k);
        if (lane == 0) sh1[wid] = fmaxf(acc + __ldg(b1 + wid), 0.0f);
    }
    __syncthreads();
    if (tid == 0) {
        float h2[5];
        #pragma unroll
        for (int j = 0; j < 5; ++j) {
            float a2 = __ldg(b2 + j);
            #pragma unroll
            for (int i = 0; i < 5; ++i) a2 = fmaf(__ldg(W2 + j * 5 + i), sh1[i], a2);
            h2[j] = fmaxf(a2, 0.0f);
        }
        float t0 = __ldg(b3);
        #pragma unroll
        for (int i = 0; i < 5; ++i) t0 = fmaf(__ldg(W3 + i), h2[i], t0);
        t0 = fabsf(t0);
        float sp   = (t0 > 20.0f) ? t0 : log1pf(expf(t0));
        float temp = fmaxf(sp, 1e-5f);
        float a    = 1.44269504088896340736f / temp;
        g_a[row] = a;
        g_b[row] = -M * a;
    }
}

// =================== K2: sum of exp + last-CTA finalize ===================
__global__ void __launch_bounds__(NT)
k2_sumexp(const float* __restrict__ inp,
          const int* __restrict__ tokens,
          float* __restrict__ out)
{
    const int row = blockIdx.x >> 2;
    const int seg = blockIdx.x & 3;
    const int tid = threadIdx.x;
    const float* x = inp + (size_t)row * VV;
    const float a = __ldg(&g_a[row]);
    const float b = __ldg(&g_b[row]);
    const int start = seg * SEGLEN;
    const int end   = min(VV, start + SEGLEN);

    float s = 0.0f;
    int i = start + tid;
    for (; i + 7 * NT < end; i += 8 * NT) {
        float v[8];
        #pragma unroll
        for (int j = 0; j < 8; j++) v[j] = __ldg(x + i + j * NT);
        #pragma unroll
        for (int j = 0; j < 8; j++) s += exp2_fast(fmaf(v[j], a, b));
    }
    for (; i < end; i += NT) s += exp2_fast(fmaf(__ldg(x + i), a, b));

    __shared__ float red[8];
    __shared__ int   sdone;
    int lane = tid & 31, w = tid >> 5;
    #pragma unroll
    for (int k = 16; k; k >>= 1) s += __shfl_xor_sync(~0u, s, k);
    if (lane == 0) red[w] = s;
    __syncthreads();
    if (tid == 0) {
        float tot = 0.0f;
        #pragma unroll
        for (int k = 0; k < NT / 32; k++) tot += red[k];
        g_part[row * SEG + seg] = tot;
        __threadfence();
        sdone = (int)atomicAdd(&g_done2[row], 1u);
    }
    __syncthreads();
    if (sdone == SEG - 1 && tid == 0) {
        __threadfence();
        float tot = g_part[row * SEG + 0] + g_part[row * SEG + 1]
                  + g_part[row * SEG + 2] + g_part[row * SEG + 3];
        int tok = tokens[row];
        tok = (tok < 0) ? 0 : ((tok >= VV) ? VV - 1 : tok);
        float xt = __ldg(x + tok);
        out[row] = exp2_fast(fmaf(xt, a, b)) / tot;
        g_done2[row] = 0u;                          // reset for next replay
    }
}

extern "C" void kernel_launch(void* const* d_in, const int* in_sizes, int n_in,
                              void* d_out, int out_size)
{
    const float* inp    = (const float*)d_in[0];
    const int*   tokens = (const int*)d_in[1];
    const float* W1     = (const float*)d_in[2];
    const float* b1     = (const float*)d_in[3];
    const float* W2     = (const float*)d_in[4];
    const float* b2     = (const float*)d_in[5];
    const float* W3     = (const float*)d_in[6];
    const float* b3     = (const float*)d_in[7];
    float*       o      = (float*)d_out;

    int N = in_sizes[1];
    if (N > MAXN) N = MAXN;

    size_t smb = (size_t)(WCAPG + FCAP) * sizeof(float);   // 9 KB
    cudaFuncSetAttribute(k1b_sortmlp, cudaFuncAttributeMaxDynamicSharedMemorySize, (int)smb);

    k0_thresh  <<<N, NT>>>(inp);
    k1_gather  <<<N * SEG, NT>>>(inp);
    k1b_sortmlp<<<N, NT, smb>>>(inp, W1, b1, W2, b2, W3, b3);
    k2_sumexp  <<<N * SEG, NT>>>(inp, tokens, o);
}

// round 11
// speedup vs baseline: 2.3395x; 1.0999x over previous
#include <cuda_runtime.h>
#include <math.h>

#define VV      50257
#define NT      256
#define SCAP    512                  // per-CTA smem winner staging
#define WCAPG   2048                 // global per-row winner cap (4 CTAs x SCAP)
#define FCAP    256                  // finalist buffer
#define TOPK    100
#define THR0    2.5f                 // static gather threshold; certificate+fallback cover any data
#define SEG     4
#define SEGLEN  12565
#define MAXN    8192

__device__ float    g_a[MAXN];
__device__ float    g_b[MAXN];
__device__ float    g_part[MAXN * SEG];
__device__ unsigned g_cnt[MAXN];     // zero-init; K1b resets for next graph replay
__device__ float    g_win[(size_t)MAXN * WCAPG];

// 2^y via round-to-int bit trick + degree-5 poly; FMA/ALU only, no MUFU.
__device__ __forceinline__ float exp2_fast(float y) {
    y = fmaxf(y, -120.0f);
    float r = y + 12582912.0f;
    int   n = __float_as_int(r) - 0x4B400000;
    float f = y - (r - 12582912.0f);
    float p = 1.3333558146428443e-3f;
    p = fmaf(p, f, 9.6181291076284772e-3f);
    p = fmaf(p, f, 5.5504108664821580e-2f);
    p = fmaf(p, f, 2.4022650695910071e-1f);
    p = fmaf(p, f, 6.9314718055994531e-1f);
    p = fmaf(p, f, 1.0f);
    return __uint_as_float(__float_as_uint(p) + ((unsigned)n << 23));
}

// ---------------- block reductions (8 warps, 256 threads) ----------------
__device__ __forceinline__ float blockMaxF(float v, float* red, int tid) {
    int lane = tid & 31, w = tid >> 5;
    #pragma unroll
    for (int k = 16; k; k >>= 1) v = fmaxf(v, __shfl_xor_sync(~0u, v, k));
    if (lane == 0) red[w] = v;
    __syncthreads();
    if (tid < 32) {
        float m = (tid < 8) ? red[tid] : -INFINITY;
        #pragma unroll
        for (int k = 4; k; k >>= 1) m = fmaxf(m, __shfl_xor_sync(~0u, m, k));
        if (tid == 0) red[0] = m;
    }
    __syncthreads();
    float r = red[0]; __syncthreads();
    return r;
}
__device__ __forceinline__ int blockSumI(int v, int* redi, int tid) {
    int lane = tid & 31, w = tid >> 5;
    #pragma unroll
    for (int k = 16; k; k >>= 1) v += __shfl_xor_sync(~0u, v, k);
    if (lane == 0) redi[w] = v;
    __syncthreads();
    if (tid < 32) {
        int s = (tid < 8) ? redi[tid] : 0;
        #pragma unroll
        for (int k = 4; k; k >>= 1) s += __shfl_xor_sync(~0u, s, k);
        if (tid == 0) redi[0] = s;
    }
    __syncthreads();
    int r = redi[0]; __syncthreads();
    return r;
}

// full-row count of (> t) from global (fallback only)
__device__ __forceinline__ int cgtGlobal(const float* __restrict__ x, float t,
                                         int tid, int* redi) {
    int c = 0;
    #pragma unroll 8
    for (int i = tid; i < VV; i += NT) c += (__ldg(x + i) > t);
    return blockSumI(c, redi, tid);
}

// =================== K1: pure stream-gather, ping-pong pipelined loads ===================
__global__ void __launch_bounds__(NT)
k1_gather(const float* __restrict__ inp)
{
    __shared__ float    swin[SCAP];
    __shared__ int      scnt;
    __shared__ unsigned sbase;

    const int row = blockIdx.x >> 2;
    const int seg = blockIdx.x & 3;
    const int tid = threadIdx.x;
    const float* x = inp + (size_t)row * VV;
    const float t = THR0;
    const int s0 = seg * SEGLEN;
    const int s1 = min(VV, s0 + SEGLEN);

    if (tid == 0) scnt = 0;
    __syncthreads();

    #define PUSH(v) do { int p = atomicAdd(&scnt, 1); \
                         if (p < SCAP) swin[p] = (v); } while (0)
    #define LOAD8(dst, k) do { const int ib = s0 + (k) * (8 * NT) + tid; \
        _Pragma("unroll") for (int j = 0; j < 8; j++) dst[j] = __ldg(x + ib + j * NT); } while (0)
    #define PROC8(v) do { \
        float m8 = fmaxf(fmaxf(fmaxf(v[0], v[1]), fmaxf(v[2], v[3])), \
                         fmaxf(fmaxf(v[4], v[5]), fmaxf(v[6], v[7]))); \
        if (m8 > t) { \
            _Pragma("unroll") for (int j = 0; j < 8; j++) if (v[j] > t) PUSH(v[j]); \
        } } while (0)

    const int nb = (s1 - s0) / (8 * NT);          // full 8-deep batches (6 per segment)
    if (nb > 0) {
        float va[8], vb[8];
        LOAD8(va, 0);
        int k = 1;
        #pragma unroll 1
        for (; k + 1 < nb; k += 2) {
            LOAD8(vb, k);                          // batch k in flight
            PROC8(va);                             // process batch k-1
            LOAD8(va, k + 1);                      // batch k+1 in flight
            PROC8(vb);                             // process batch k
        }
        if (k < nb) {                              // one unpaired batch remains
            LOAD8(vb, k);
            PROC8(va);
            PROC8(vb);
        } else {
            PROC8(va);
        }
    }
    for (int i = s0 + nb * (8 * NT) + tid; i < s1; i += NT) {   // tail (<2048 elems)
        float v = __ldg(x + i);
        if (v > t) PUSH(v);
    }
    #undef PROC8
    #undef LOAD8
    #undef PUSH

    __syncthreads();
    int c = scnt;
    if (tid == 0)
        sbase = atomicAdd(&g_cnt[row], (c > SCAP) ? (unsigned)(WCAPG + 1) : (unsigned)c);
    __syncthreads();
    if (c <= SCAP) {
        unsigned base = sbase;
        for (int i = tid; i < c; i += NT) {
            unsigned p = base + (unsigned)i;
            if (p < WCAPG) g_win[(size_t)row * WCAPG + p] = swin[i];
        }
    }
}

// =================== K1b: per-row select + sort + MLP ===================
extern __shared__ float smk1b[];

__global__ void __launch_bounds__(NT)
k1b_sortmlp(const float* __restrict__ inp,
            const float* __restrict__ W1, const float* __restrict__ b1,
            const float* __restrict__ W2, const float* __restrict__ b2,
            const float* __restrict__ W3, const float* __restrict__ b3)
{
    float* win = smk1b;               // [WCAPG]
    float* buf = smk1b + WCAPG;       // [FCAP]
    __shared__ float redf[8];
    __shared__ int   redi[8];
    __shared__ int   sCnt;
    __shared__ float sh1[5];

    const int tid  = threadIdx.x;
    const int lane = tid & 31;
    const int wid  = tid >> 5;
    const int row  = blockIdx.x;
    const float* x = inp + (size_t)row * VV;

    const unsigned cntRaw = g_cnt[row];
    float tSel = THR0;
    int cnt = (int)min(cntRaw, (unsigned)WCAPG);

    for (int i = tid; i < cnt; i += NT) win[i] = g_win[(size_t)row * WCAPG + i];
    if (tid == 0) sCnt = 0;
    __syncthreads();

    const int bad = (cntRaw > (unsigned)WCAPG) || (cnt < TOPK);
    float M;

    if (bad) {
        // ---- rare exact fallback: exact max + global bisection + gather ----
        float mx = -INFINITY;
        #pragma unroll 8
        for (int i = tid; i < VV; i += NT) mx = fmaxf(mx, __ldg(x + i));
        M = blockMaxF(mx, redf, tid);
        float gap = 8.0f, lo = M - gap, hi = M;
        int c = cgtGlobal(x, lo, tid, redi);
        for (int e = 0; e < 12 && c < TOPK; e++) {
            gap *= 4.0f; lo = M - gap;
            c = cgtGlobal(x, lo, tid, redi);
        }
        float ts = hi; int found = 0;
        if (c >= TOPK && c <= FCAP) { ts = lo; found = 1; }
        for (int it = 0; it < 50 && !found; it++) {
            float mid = 0.5f * (lo + hi);
            if (mid <= lo || mid >= hi) break;        // tie plateau -> hi
            c = cgtGlobal(x, mid, tid, redi);
            if (c >= TOPK && c <= FCAP) { ts = mid; found = 1; }
            else if (c > FCAP) lo = mid; else hi = mid;
        }
        tSel = ts;
        #pragma unroll 4
        for (int i = tid; i < VV; i += NT) {
            float v = __ldg(x + i);
            if (v > tSel) { int p = atomicAdd(&sCnt, 1); if (p < FCAP) buf[p] = v; }
        }
        __syncthreads();
    } else {
        // exact row max = max of winners (cnt >= TOPK means max > THR0, so gathered)
        float mx = -INFINITY;
        for (int i = tid; i < cnt; i += NT) mx = fmaxf(mx, win[i]);
        M = blockMaxF(mx, redf, tid);
        if (cnt > FCAP) {
            float lo = tSel, hi = M;
            int found = 0;
            float ts = tSel;
            for (int it = 0; it < 40 && !found; it++) {
                float mid = 0.5f * (lo + hi);
                if (mid <= lo || mid >= hi) { ts = hi; break; }   // tie plateau
                int c = 0;
                for (int i = tid; i < cnt; i += NT) c += (win[i] > mid);
                c = blockSumI(c, redi, tid);
                if (c >= TOPK && c <= FCAP) { ts = mid; found = 1; }
                else if (c > FCAP) lo = mid; else hi = mid;
            }
            if (!found && ts == tSel) ts = hi;
            tSel = ts;
        }
        for (int i = tid; i < cnt; i += NT) {
            float v = win[i];
            if (v > tSel) { int p = atomicAdd(&sCnt, 1); if (p < FCAP) buf[p] = v; }
        }
        __syncthreads();
    }

    int bc = min(sCnt, FCAP);
    if (tid >= bc) buf[tid] = -INFINITY;          // pad (NT == FCAP)
    __syncthreads();

    // ---- bitonic sort 256 descending ----
    #pragma unroll 1
    for (int k = 2; k <= FCAP; k <<= 1) {
        #pragma unroll 1
        for (int j = k >> 1; j > 0; j >>= 1) {
            int i = tid, ixj = i ^ j;
            if (ixj > i) {
                float va = buf[i], vb = buf[ixj];
                bool desc = ((i & k) == 0);
                if (desc ? (va < vb) : (va > vb)) { buf[i] = vb; buf[ixj] = va; }
            }
            __syncthreads();
        }
    }
    // tie-plateau fill: missing top-k entries equal tSel by construction
    if (tid < TOPK && tid >= bc) buf[tid] = tSel;
    __syncthreads();

    // ---- tiny MLP -> temperature -> (a, b) ----
    if (wid < 5) {
        float acc = 0.0f;
        #pragma unroll
        for (int i = lane; i < TOPK; i += 32)
            acc = fmaf(__ldg(W1 + wid * TOPK + i), buf[i], acc);
        #pragma unroll
        for (int k = 16; k; k >>= 1) acc += __shfl_xor_sync(~0u, acc, k);
        if (lane == 0) sh1[wid] = fmaxf(acc + __ldg(b1 + wid), 0.0f);
    }
    __syncthreads();
    if (tid == 0) {
        float h2[5];
        #pragma unroll
        for (int j = 0; j < 5; ++j) {
            float a2 = __ldg(b2 + j);
            #pragma unroll
            for (int i = 0; i < 5; ++i) a2 = fmaf(__ldg(W2 + j * 5 + i), sh1[i], a2);
            h2[j] = fmaxf(a2, 0.0f);
        }
        float t0 = __ldg(b3);
        #pragma unroll
        for (int i = 0; i < 5; ++i) t0 = fmaf(__ldg(W3 + i), h2[i], t0);
        t0 = fabsf(t0);
        float sp   = (t0 > 20.0f) ? t0 : log1pf(expf(t0));
        float temp = fmaxf(sp, 1e-5f);
        float a    = 1.44269504088896340736f / temp;
        g_a[row] = a;
        g_b[row] = -M * a;
        g_cnt[row] = 0u;          // reset for next graph replay (ordered by stream)
    }
}

// =================== K2: pure segmented sum of exp ===================
__global__ void __launch_bounds__(NT)
k2_sumexp(const float* __restrict__ inp)
{
    const int row = blockIdx.x >> 2;
    const int seg = blockIdx.x & 3;
    const int tid = threadIdx.x;
    const float* x = inp + (size_t)row * VV;
    const float a = __ldg(&g_a[row]);
    const float b = __ldg(&g_b[row]);
    const int start = seg * SEGLEN;
    const int end   = min(VV, start + SEGLEN);

    float s = 0.0f;
    int i = start + tid;
    for (; i + 7 * NT < end; i += 8 * NT) {
        float v[8];
        #pragma unroll
        for (int j = 0; j < 8; j++) v[j] = __ldg(x + i + j * NT);
        #pragma unroll
        for (int j = 0; j < 8; j++) s += exp2_fast(fmaf(v[j], a, b));
    }
    for (; i < end; i += NT) s += exp2_fast(fmaf(__ldg(x + i), a, b));

    __shared__ float red[8];
    int lane = tid & 31, w = tid >> 5;
    #pragma unroll
    for (int k = 16; k; k >>= 1) s += __shfl_xor_sync(~0u, s, k);
    if (lane == 0) red[w] = s;
    __syncthreads();
    if (tid == 0) {
        float tot = 0.0f;
        #pragma unroll
        for (int k = 0; k < NT / 32; k++) tot += red[k];
        g_part[row * SEG + seg] = tot;
    }
}

__global__ void k3_final(const float* __restrict__ inp,
                         const int* __restrict__ tokens,
                         float* __restrict__ out, int nrows)
{
    int r = blockIdx.x * blockDim.x + threadIdx.x;
    if (r >= nrows) return;
    float s = g_part[r * SEG + 0] + g_part[r * SEG + 1]
            + g_part[r * SEG + 2] + g_part[r * SEG + 3];
    int tok = tokens[r];
    tok = (tok < 0) ? 0 : ((tok >= VV) ? VV - 1 : tok);
    float xt = __ldg(inp + (size_t)r * VV + tok);
    out[r] = exp2_fast(fmaf(xt, g_a[r], g_b[r])) / s;
}

extern "C" void kernel_launch(void* const* d_in, const int* in_sizes, int n_in,
                              void* d_out, int out_size)
{
    const float* inp    = (const float*)d_in[0];
    const int*   tokens = (const int*)d_in[1];
    const float* W1     = (const float*)d_in[2];
    const float* b1     = (const float*)d_in[3];
    const float* W2     = (const float*)d_in[4];
    const float* b2     = (const float*)d_in[5];
    const float* W3     = (const float*)d_in[6];
    const float* b3     = (const float*)d_in[7];
    float*       o      = (float*)d_out;

    int N = in_sizes[1];
    if (N > MAXN) N = MAXN;

    size_t smb = (size_t)(WCAPG + FCAP) * sizeof(float);   // 9 KB
    cudaFuncSetAttribute(k1b_sortmlp, cudaFuncAttributeMaxDynamicSharedMemorySize, (int)smb);

    k1_gather  <<<N * SEG, NT>>>(inp);
    k1b_sortmlp<<<N, NT, smb>>>(inp, W1, b1, W2, b2, W3, b3);
    k2_sumexp  <<<N * SEG, NT>>>(inp);
    k3_final   <<<(N + 255) / 256, 256>>>(inp, tokens, o, N);
}